// round 11
// baseline (speedup 1.0000x reference)
#include <cuda_runtime.h>
#include <cuda_bf16.h>
#include <cstdint>
#include <math.h>

#define BB      128
#define DD      (512*512)          // 262144
#define KT      64                 // k elements per stage
#define NTILES  (DD/KT)            // 4096
#define NSLICE  148                // k-slices; grid = 2*NSLICE (column halves)
#define THREADS 512
#define NCH     4                  // reduction chunks (148 = 4*37)
#define CPC     37
#define STAGE   49152              // 48KB per stage: Xh(16K) Xl(16K) Yh(8K) Yl(8K)
#define SMEM_TOTAL (2*STAGE)       // 96KB -> 2 CTAs/SM

// ---- scratch (__device__ globals; allocation-free rule) ----
__device__ float g_part[(size_t)NSLICE*BB*BB];  // per-slice partial dots
__device__ float g_xn2p[NSLICE*BB];
__device__ float g_yn2p[NSLICE*BB];
__device__ float g_p2[BB*BB*NCH];
__device__ float g_xc[BB*NCH];
__device__ float g_yc[BB*NCH];
__device__ int   g_it1, g_it10, g_tick;

__device__ __forceinline__ uint32_t smem_u32(const void* p) {
    uint32_t a;
    asm("{ .reg .u64 t; cvta.to.shared.u64 t, %1; cvt.u32.u64 %0, t; }" : "=r"(a) : "l"(p));
    return a;
}
#define SW128(o) ((uint32_t)(o) ^ ((((uint32_t)(o)) >> 3) & 0x70))

__device__ __forceinline__ void cvt_hilo(float a, float b, uint32_t& h, uint32_t& l) {
    asm("cvt.rn.bf16x2.f32 %0, %1, %2;" : "=r"(h) : "f"(b), "f"(a));
    float fa = __uint_as_float(h << 16);
    float fb = __uint_as_float(h & 0xffff0000u);
    float la = a - fa, lb = b - fb;
    asm("cvt.rn.bf16x2.f32 %0, %1, %2;" : "=r"(l) : "f"(lb), "f"(la));
}

#define LDSM4(r, addr)                                                          \
    asm volatile("ldmatrix.sync.aligned.m8n8.x4.shared.b16 {%0,%1,%2,%3}, [%4];"\
        : "=r"((r)[0]), "=r"((r)[1]), "=r"((r)[2]), "=r"((r)[3]) : "r"(addr))

#define MMA16816(d, a0, a1, a2, a3, b0, b1)                                     \
    asm volatile("mma.sync.aligned.m16n8k16.row.col.f32.bf16.bf16.f32 "         \
        "{%0,%1,%2,%3}, {%4,%5,%6,%7}, {%8,%9}, {%0,%1,%2,%3};"                 \
        : "+f"((d)[0]), "+f"((d)[1]), "+f"((d)[2]), "+f"((d)[3])                \
        : "r"(a0), "r"(a1), "r"(a2), "r"(a3), "r"(b0), "r"(b1))

__global__ void __launch_bounds__(THREADS, 2)
gemm_tc_kernel(const float* __restrict__ X, const float* __restrict__ Y) {
    extern __shared__ char smem[];
    const uint32_t sbase = smem_u32(smem);
    const int t    = threadIdx.x;
    const int lane = t & 31;
    const int w    = t >> 5;          // warps 0-7: producers; 8-15: consumers
    const int c    = blockIdx.x >> 1; // k-slice
    const int half = blockIdx.x & 1;  // column half (Y rows half*64..half*64+63)

    const int t0 = (int)(((long long)c       * NTILES) / NSLICE);
    const int t1 = (int)(((long long)(c + 1) * NTILES) / NSLICE);
    const int NT = t1 - t0;

    if (w >= 8) {
        // -------- CONSUMER: 32x32 output tile per warp (X 128 x Y-half 64) --------
        const int cw = w - 8;
        const int rb = (cw >> 1) * 32;    // X row band (4 bands)
        const int cb = (cw & 1) * 32;     // Y col half-of-half (2)

        const int a_row = rb + (lane & 7) + ((lane >> 3) & 1) * 8;
        const int a_kb  = ((lane >> 4) & 1) * 16;
        const int b_row = cb + (lane & 7) + ((lane >> 3) & 1) * 8;
        const int b_kb  = ((lane >> 4) & 1) * 16;

        float acc[8][4];
        #pragma unroll
        for (int j = 0; j < 8; j++)
            #pragma unroll
            for (int q = 0; q < 4; q++) acc[j][q] = 0.0f;

        __syncthreads();   // stage 0 ready

        for (int s = 0; s < NT; s++) {
            const uint32_t sb = sbase + (uint32_t)(s & 1) * STAGE;
            const uint32_t xh = sb;
            const uint32_t xl = sb + 16384;
            const uint32_t yh = sb + 32768;
            const uint32_t yl = sb + 40960;
            #pragma unroll
            for (int kk = 0; kk < 4; kk++) {
                const uint32_t aoff0 = SW128(a_row * 128 + kk * 32 + a_kb);
                const uint32_t aoff1 = SW128((a_row + 16) * 128 + kk * 32 + a_kb);
                const uint32_t boff0 = SW128(b_row * 128 + kk * 32 + b_kb);
                const uint32_t boff1 = SW128((b_row + 16) * 128 + kk * 32 + b_kb);
                uint32_t ah[8], al[8], bh[8], bl[8];
                LDSM4(ah + 0, xh + aoff0);
                LDSM4(ah + 4, xh + aoff1);
                LDSM4(al + 0, xl + aoff0);
                LDSM4(al + 4, xl + aoff1);
                LDSM4(bh + 0, yh + boff0);
                LDSM4(bh + 4, yh + boff1);
                // hh term (8 independent accumulators)
                #pragma unroll
                for (int m = 0; m < 2; m++) {
                    MMA16816(acc[m*4+0], ah[m*4+0],ah[m*4+1],ah[m*4+2],ah[m*4+3], bh[0], bh[2]);
                    MMA16816(acc[m*4+1], ah[m*4+0],ah[m*4+1],ah[m*4+2],ah[m*4+3], bh[1], bh[3]);
                    MMA16816(acc[m*4+2], ah[m*4+0],ah[m*4+1],ah[m*4+2],ah[m*4+3], bh[4], bh[6]);
                    MMA16816(acc[m*4+3], ah[m*4+0],ah[m*4+1],ah[m*4+2],ah[m*4+3], bh[5], bh[7]);
                }
                LDSM4(bl + 0, yl + boff0);
                LDSM4(bl + 4, yl + boff1);
                // hl term
                #pragma unroll
                for (int m = 0; m < 2; m++) {
                    MMA16816(acc[m*4+0], ah[m*4+0],ah[m*4+1],ah[m*4+2],ah[m*4+3], bl[0], bl[2]);
                    MMA16816(acc[m*4+1], ah[m*4+0],ah[m*4+1],ah[m*4+2],ah[m*4+3], bl[1], bl[3]);
                    MMA16816(acc[m*4+2], ah[m*4+0],ah[m*4+1],ah[m*4+2],ah[m*4+3], bl[4], bl[6]);
                    MMA16816(acc[m*4+3], ah[m*4+0],ah[m*4+1],ah[m*4+2],ah[m*4+3], bl[5], bl[7]);
                }
                // lh term
                #pragma unroll
                for (int m = 0; m < 2; m++) {
                    MMA16816(acc[m*4+0], al[m*4+0],al[m*4+1],al[m*4+2],al[m*4+3], bh[0], bh[2]);
                    MMA16816(acc[m*4+1], al[m*4+0],al[m*4+1],al[m*4+2],al[m*4+3], bh[1], bh[3]);
                    MMA16816(acc[m*4+2], al[m*4+0],al[m*4+1],al[m*4+2],al[m*4+3], bh[4], bh[6]);
                    MMA16816(acc[m*4+3], al[m*4+0],al[m*4+1],al[m*4+2],al[m*4+3], bh[5], bh[7]);
                }
            }
            __syncthreads();
        }

        // epilogue: per-slice partial dots, columns offset by half*64
        float* base = &g_part[(size_t)c * (BB * BB)];
        const int r0 = rb + (lane >> 2);
        const int c0 = half * 64 + cb + (lane & 3) * 2;
        #pragma unroll
        for (int m = 0; m < 2; m++)
            #pragma unroll
            for (int n = 0; n < 4; n++) {
                const int j = m * 4 + n;
                const int col = c0 + n * 8;
                *(float2*)(base + (size_t)(r0 + m*16)     * BB + col) = make_float2(acc[j][0], acc[j][1]);
                *(float2*)(base + (size_t)(r0 + m*16 + 8) * BB + col) = make_float2(acc[j][2], acc[j][3]);
            }
    } else {
        // -------- PRODUCER: 256 threads, 192 rows (X 0..127, Y-local 0..63) --------
        const int tp   = w * 32 + lane;         // 0..255
        const int prow = tp >> 4;               // row group 0..15
        const int pf4  = tp & 15;               // float4 column
        const int h64  = half * 64;

        float sn[12];
        #pragma unroll
        for (int i = 0; i < 12; i++) sn[i] = 0.f;

        float4 vv[2][6];                        // two halves of 6 rows each

        auto load_half = [&](int kt, int h) {
            const long long kb = (long long)kt * KT + pf4 * 4;
            #pragma unroll
            for (int i = 0; i < 6; i++) {
                const int ii = 6 * h + i;
                const int cr = prow + 16 * ii;  // combined row 0..191
                const float* base = (cr < 128)
                    ? (X + (long long)cr * DD)
                    : (Y + (long long)(h64 + cr - 128) * DD);
                vv[h][i] = __ldg((const float4*)(base + kb));
            }
        };
        auto store_half = [&](int p, int h) {
            char* sb = smem + p * STAGE;
            #pragma unroll
            for (int i = 0; i < 6; i++) {
                const int ii = 6 * h + i;
                const int cr = prow + 16 * ii;
                const bool isX = (cr < 128);
                const int lrow = isX ? cr : cr - 128;
                const uint32_t off = SW128(lrow * 128 + pf4 * 8);
                char* th = sb + (isX ? 0     : 32768);
                char* tl = sb + (isX ? 16384 : 40960);
                const float4 v = vv[h][i];
                sn[ii] += v.x*v.x + v.y*v.y + v.z*v.z + v.w*v.w;
                uint32_t h0, l0, h1, l1;
                cvt_hilo(v.x, v.y, h0, l0);
                cvt_hilo(v.z, v.w, h1, l1);
                *(uint2*)(th + off) = make_uint2(h0, h1);
                *(uint2*)(tl + off) = make_uint2(l0, l1);
            }
        };

        load_half(t0, 0); load_half(t0, 1);
        store_half(0, 0); store_half(0, 1);
        if (NT > 1) { load_half(t0 + 1, 0); load_half(t0 + 1, 1); }
        __syncthreads();   // stage 0 ready

        for (int s = 0; s < NT; s++) {
            if (s + 1 < NT) {
                const int p = (s + 1) & 1;
                store_half(p, 0);
                if (s + 2 < NT) load_half(t0 + s + 2, 0);
                store_half(p, 1);
                if (s + 2 < NT) load_half(t0 + s + 2, 1);
            }
            __syncthreads();
        }

        // norm partials: reduce over 16 f4-lanes per row
        #pragma unroll
        for (int i = 0; i < 12; i++) {
            float a = sn[i];
            #pragma unroll
            for (int o = 8; o >= 1; o >>= 1)
                a += __shfl_xor_sync(0xffffffffu, a, o);
            if (pf4 == 0) {
                const int cr = prow + 16 * i;
                if (cr < 128) {
                    if (half == 0) g_xn2p[c * BB + cr] = a;  // X norms once per slice
                } else {
                    g_yn2p[c * BB + h64 + (cr - 128)] = a;   // each half owns its 64
                }
            }
        }
    }
}

// Phase A: chunked reduction over 148 slices (4 chunks x 37). Deterministic.
__global__ void reduce_kernel() {
    const int gid = blockIdx.x * blockDim.x + threadIdx.x;   // 0..65535
    const int ch  = gid >> 14;
    const int idx = gid & 16383;
    if (gid == 0) { g_it1 = 0; g_it10 = 0; g_tick = 0; }
    const int c0 = ch * CPC;
    float s = 0.f;
    #pragma unroll
    for (int k = 0; k < CPC; k++) s += g_part[(size_t)(c0 + k) * (BB * BB) + idx];
    g_p2[idx * NCH + ch] = s;
    if (idx < BB) {
        float s2 = 0.f;
        #pragma unroll
        for (int k = 0; k < CPC; k++) s2 += g_xn2p[(c0 + k) * BB + idx];
        g_xc[idx * NCH + ch] = s2;
    } else if (idx < 2 * BB) {
        const int r = idx - BB;
        float s2 = 0.f;
        #pragma unroll
        for (int k = 0; k < CPC; k++) s2 += g_yn2p[(c0 + k) * BB + r];
        g_yc[r * NCH + ch] = s2;
    }
}

// parallel finalize: CTA j handles sim column j. JAX ties: lower index wins.
__global__ void finalize_kernel(float* __restrict__ out) {
    __shared__ float s_vd;
    __shared__ int s_gt, s_eqb;
    const int j = blockIdx.x;
    const int i = threadIdx.x;

    const float4 dv = *(const float4*)&g_p2[(i * BB + j) * NCH];
    const float dots = (dv.x + dv.y) + (dv.z + dv.w);
    const float4 xv = *(const float4*)&g_xc[i * NCH];
    const float xni = sqrtf((xv.x + xv.y) + (xv.z + xv.w));
    const float4 yv = *(const float4*)&g_yc[j * NCH];
    const float ynj = sqrtf((yv.x + yv.y) + (yv.z + yv.w));
    const float v = dots / fmaxf(xni * ynj, 1e-8f);

    if (i == 0) { s_gt = 0; s_eqb = 0; }
    if (i == j) s_vd = v;
    __syncthreads();
    const float vd = s_vd;

    const bool gt  = (i != j) && (v > vd);
    const bool eqb = (i != j) && (v == vd) && (i < j);
    const unsigned mgt  = __ballot_sync(0xffffffffu, gt);
    const unsigned meqb = __ballot_sync(0xffffffffu, eqb);
    if ((i & 31) == 0) {
        if (mgt)  atomicAdd(&s_gt,  __popc(mgt));
        if (meqb) atomicAdd(&s_eqb, __popc(meqb));
    }
    __syncthreads();

    if (i == 0) {
        const int rank = s_gt + s_eqb;
        atomicAdd(&g_it1,  (rank == 0) ? 1 : 0);
        atomicAdd(&g_it10, (rank < 10) ? 1 : 0);
        __threadfence();
        const int tick = atomicAdd(&g_tick, 1);
        if (tick == BB - 1) {
            __threadfence();
            out[0] = (float)g_it1  / (float)BB;
            out[1] = (float)g_it10 / (float)BB;
        }
    }
}

extern "C" void kernel_launch(void* const* d_in, const int* in_sizes, int n_in,
                              void* d_out, int out_size) {
    const float* Z = (const float*)d_in[0];
    const float* Y = (const float*)d_in[1];
    float* out = (float*)d_out;

    cudaFuncSetAttribute(gemm_tc_kernel, cudaFuncAttributeMaxDynamicSharedMemorySize, SMEM_TOTAL);
    gemm_tc_kernel<<<2 * NSLICE, THREADS, SMEM_TOTAL>>>(Z, Y);
    reduce_kernel<<<256, 256>>>();
    finalize_kernel<<<BB, BB>>>(out);
}

// round 12
// speedup vs baseline: 1.2549x; 1.2549x over previous
#include <cuda_runtime.h>
#include <cuda_bf16.h>
#include <cstdint>
#include <math.h>

#define BB      128
#define DD      (512*512)          // 262144
#define KT      64                 // k elements per stage
#define NTILES  (DD/KT)            // 4096
#define NCTA    148
#define THREADS 512
#define NCH     4                  // reduction chunks (148 = 4*37)
#define CPC     37

// ---- scratch (__device__ globals; allocation-free rule) ----
__device__ float g_part[(size_t)NCTA*BB*BB];   // per-CTA partial dots [c][m][n]
__device__ float g_xn2p[NCTA*BB];
__device__ float g_yn2p[NCTA*BB];
__device__ float g_p2[BB*BB*NCH];              // chunked dots [idx][ch]
__device__ float g_xc[BB*NCH];
__device__ float g_yc[BB*NCH];
__device__ int   g_it1, g_it10, g_tick;

__device__ __forceinline__ uint32_t smem_u32(const void* p) {
    uint32_t a;
    asm("{ .reg .u64 t; cvta.to.shared.u64 t, %1; cvt.u32.u64 %0, t; }" : "=r"(a) : "l"(p));
    return a;
}
#define SW128(o) ((uint32_t)(o) ^ ((((uint32_t)(o)) >> 3) & 0x70))

// fp32 pair -> packed bf16x2 hi + bf16x2 lo (memory order [a,b], a in low half)
__device__ __forceinline__ void cvt_hilo(float a, float b, uint32_t& h, uint32_t& l) {
    asm("cvt.rn.bf16x2.f32 %0, %1, %2;" : "=r"(h) : "f"(b), "f"(a));
    float fa = __uint_as_float(h << 16);
    float fb = __uint_as_float(h & 0xffff0000u);
    float la = a - fa, lb = b - fb;
    asm("cvt.rn.bf16x2.f32 %0, %1, %2;" : "=r"(l) : "f"(lb), "f"(la));
}

#define LDSM4(r, addr)                                                          \
    asm volatile("ldmatrix.sync.aligned.m8n8.x4.shared.b16 {%0,%1,%2,%3}, [%4];"\
        : "=r"((r)[0]), "=r"((r)[1]), "=r"((r)[2]), "=r"((r)[3]) : "r"(addr))

#define MMA16816(d, a0, a1, a2, a3, b0, b1)                                     \
    asm volatile("mma.sync.aligned.m16n8k16.row.col.f32.bf16.bf16.f32 "         \
        "{%0,%1,%2,%3}, {%4,%5,%6,%7}, {%8,%9}, {%0,%1,%2,%3};"                 \
        : "+f"((d)[0]), "+f"((d)[1]), "+f"((d)[2]), "+f"((d)[3])                \
        : "r"(a0), "r"(a1), "r"(a2), "r"(a3), "r"(b0), "r"(b1))

// SMEM: 2 stages x 4 tiles (Xh,Xl,Yh,Yl), each 128 rows x 128B (SW128) = 16KB
#define TILE_OFF(p, w) ((p)*65536 + (w)*16384)
#define SMEM_TOTAL (2*65536)

__global__ void __launch_bounds__(THREADS, 1)
gemm_tc_kernel(const float* __restrict__ X, const float* __restrict__ Y) {
    extern __shared__ char smem[];
    const uint32_t sbase = smem_u32(smem);
    const int t    = threadIdx.x;
    const int lane = t & 31;
    const int w    = t >> 5;          // warps 0-7: producers; 8-15: consumers (hi-wid priority)
    const int c    = blockIdx.x;

    const int t0 = (int)(((long long)c       * NTILES) / NCTA);
    const int t1 = (int)(((long long)(c + 1) * NTILES) / NCTA);
    const int NT = t1 - t0;

    if (w >= 8) {
        // ---------------- CONSUMER: 32x64 tile, software-pipelined fragments ----------------
        const int cw = w - 8;
        const int rb = (cw >> 1) * 32;     // row band
        const int cb = (cw & 1) * 64;      // col half

        const int a_row = rb + (lane & 7) + ((lane >> 3) & 1) * 8;
        const int a_kb  = ((lane >> 4) & 1) * 16;
        const int b_row = cb + (lane & 7) + ((lane >> 3) & 1) * 8;
        const int b_kb  = ((lane >> 4) & 1) * 16;

        float acc[16][4];
        #pragma unroll
        for (int j = 0; j < 16; j++)
            #pragma unroll
            for (int q = 0; q < 4; q++) acc[j][q] = 0.0f;

        uint32_t ah[2][8];   // A-hi double buffer across kk

        __syncthreads();   // stage 0 ready

        for (int s = 0; s < NT; s++) {
            const int p = s & 1;
            const uint32_t xh = sbase + TILE_OFF(p, 0);
            const uint32_t xl = sbase + TILE_OFF(p, 1);
            const uint32_t yh = sbase + TILE_OFF(p, 2);
            const uint32_t yl = sbase + TILE_OFF(p, 3);

            // preload A-hi for kk=0
            {
                const uint32_t a0 = SW128(a_row * 128 + a_kb);
                const uint32_t a1 = SW128((a_row + 16) * 128 + a_kb);
                LDSM4(ah[0] + 0, xh + a0);
                LDSM4(ah[0] + 4, xh + a1);
            }

            #pragma unroll
            for (int kk = 0; kk < 4; kk++) {
                const int cur = kk & 1, nxt = cur ^ 1;
                uint32_t al[8], bh0[8], bh1[8], bl[8];

                // prefetch A-hi for kk+1 (lands under this kk's MMAs)
                if (kk < 3) {
                    const uint32_t an0 = SW128(a_row * 128 + (kk + 1) * 32 + a_kb);
                    const uint32_t an1 = SW128((a_row + 16) * 128 + (kk + 1) * 32 + a_kb);
                    LDSM4(ah[nxt] + 0, xh + an0);
                    LDSM4(ah[nxt] + 4, xh + an1);
                }
                // A-lo and B-hi(nh=0)
                const uint32_t ao0 = SW128(a_row * 128 + kk * 32 + a_kb);
                const uint32_t ao1 = SW128((a_row + 16) * 128 + kk * 32 + a_kb);
                LDSM4(al + 0, xl + ao0);
                LDSM4(al + 4, xl + ao1);
                const uint32_t b00 = SW128(b_row * 128 + kk * 32 + b_kb);
                const uint32_t b01 = SW128((b_row + 16) * 128 + kk * 32 + b_kb);
                LDSM4(bh0 + 0, yh + b00);
                LDSM4(bh0 + 4, yh + b01);

                // hh(nh=0): ah[cur] ready from previous kk
                #pragma unroll
                for (int m = 0; m < 2; m++) {
                    MMA16816(acc[m*8+0], ah[cur][m*4+0],ah[cur][m*4+1],ah[cur][m*4+2],ah[cur][m*4+3], bh0[0], bh0[2]);
                    MMA16816(acc[m*8+1], ah[cur][m*4+0],ah[cur][m*4+1],ah[cur][m*4+2],ah[cur][m*4+3], bh0[1], bh0[3]);
                    MMA16816(acc[m*8+2], ah[cur][m*4+0],ah[cur][m*4+1],ah[cur][m*4+2],ah[cur][m*4+3], bh0[4], bh0[6]);
                    MMA16816(acc[m*8+3], ah[cur][m*4+0],ah[cur][m*4+1],ah[cur][m*4+2],ah[cur][m*4+3], bh0[5], bh0[7]);
                }
                // B-lo(nh=0) lands under hh
                LDSM4(bl + 0, yl + b00);
                LDSM4(bl + 4, yl + b01);
                // hl(nh=0)
                #pragma unroll
                for (int m = 0; m < 2; m++) {
                    MMA16816(acc[m*8+0], ah[cur][m*4+0],ah[cur][m*4+1],ah[cur][m*4+2],ah[cur][m*4+3], bl[0], bl[2]);
                    MMA16816(acc[m*8+1], ah[cur][m*4+0],ah[cur][m*4+1],ah[cur][m*4+2],ah[cur][m*4+3], bl[1], bl[3]);
                    MMA16816(acc[m*8+2], ah[cur][m*4+0],ah[cur][m*4+1],ah[cur][m*4+2],ah[cur][m*4+3], bl[4], bl[6]);
                    MMA16816(acc[m*8+3], ah[cur][m*4+0],ah[cur][m*4+1],ah[cur][m*4+2],ah[cur][m*4+3], bl[5], bl[7]);
                }
                // B-hi(nh=1) lands under lh(nh=0)
                const uint32_t b10 = SW128((b_row + 32) * 128 + kk * 32 + b_kb);
                const uint32_t b11 = SW128((b_row + 48) * 128 + kk * 32 + b_kb);
                LDSM4(bh1 + 0, yh + b10);
                LDSM4(bh1 + 4, yh + b11);
                // lh(nh=0)
                #pragma unroll
                for (int m = 0; m < 2; m++) {
                    MMA16816(acc[m*8+0], al[m*4+0],al[m*4+1],al[m*4+2],al[m*4+3], bh0[0], bh0[2]);
                    MMA16816(acc[m*8+1], al[m*4+0],al[m*4+1],al[m*4+2],al[m*4+3], bh0[1], bh0[3]);
                    MMA16816(acc[m*8+2], al[m*4+0],al[m*4+1],al[m*4+2],al[m*4+3], bh0[4], bh0[6]);
                    MMA16816(acc[m*8+3], al[m*4+0],al[m*4+1],al[m*4+2],al[m*4+3], bh0[5], bh0[7]);
                }
                // hh(nh=1)
                #pragma unroll
                for (int m = 0; m < 2; m++) {
                    MMA16816(acc[m*8+4], ah[cur][m*4+0],ah[cur][m*4+1],ah[cur][m*4+2],ah[cur][m*4+3], bh1[0], bh1[2]);
                    MMA16816(acc[m*8+5], ah[cur][m*4+0],ah[cur][m*4+1],ah[cur][m*4+2],ah[cur][m*4+3], bh1[1], bh1[3]);
                    MMA16816(acc[m*8+6], ah[cur][m*4+0],ah[cur][m*4+1],ah[cur][m*4+2],ah[cur][m*4+3], bh1[4], bh1[6]);
                    MMA16816(acc[m*8+7], ah[cur][m*4+0],ah[cur][m*4+1],ah[cur][m*4+2],ah[cur][m*4+3], bh1[5], bh1[7]);
                }
                // B-lo(nh=1) lands under hh(nh=1)
                LDSM4(bl + 0, yl + b10);
                LDSM4(bl + 4, yl + b11);
                // hl(nh=1)
                #pragma unroll
                for (int m = 0; m < 2; m++) {
                    MMA16816(acc[m*8+4], ah[cur][m*4+0],ah[cur][m*4+1],ah[cur][m*4+2],ah[cur][m*4+3], bl[0], bl[2]);
                    MMA16816(acc[m*8+5], ah[cur][m*4+0],ah[cur][m*4+1],ah[cur][m*4+2],ah[cur][m*4+3], bl[1], bl[3]);
                    MMA16816(acc[m*8+6], ah[cur][m*4+0],ah[cur][m*4+1],ah[cur][m*4+2],ah[cur][m*4+3], bl[4], bl[6]);
                    MMA16816(acc[m*8+7], ah[cur][m*4+0],ah[cur][m*4+1],ah[cur][m*4+2],ah[cur][m*4+3], bl[5], bl[7]);
                }
                // lh(nh=1)
                #pragma unroll
                for (int m = 0; m < 2; m++) {
                    MMA16816(acc[m*8+4], al[m*4+0],al[m*4+1],al[m*4+2],al[m*4+3], bh1[0], bh1[2]);
                    MMA16816(acc[m*8+5], al[m*4+0],al[m*4+1],al[m*4+2],al[m*4+3], bh1[1], bh1[3]);
                    MMA16816(acc[m*8+6], al[m*4+0],al[m*4+1],al[m*4+2],al[m*4+3], bh1[4], bh1[6]);
                    MMA16816(acc[m*8+7], al[m*4+0],al[m*4+1],al[m*4+2],al[m*4+3], bh1[5], bh1[7]);
                }
            }
            __syncthreads();
        }

        // epilogue: per-CTA partial dots
        float* base = &g_part[(size_t)c * (BB * BB)];
        const int r0 = rb + (lane >> 2);
        const int c0 = cb + (lane & 3) * 2;
        #pragma unroll
        for (int m = 0; m < 2; m++)
            #pragma unroll
            for (int nh = 0; nh < 2; nh++)
                #pragma unroll
                for (int jj = 0; jj < 4; jj++) {
                    const int j = m * 8 + nh * 4 + jj;
                    const int col = c0 + nh * 32 + jj * 8;
                    *(float2*)(base + (size_t)(r0 + m*16)     * BB + col) = make_float2(acc[j][0], acc[j][1]);
                    *(float2*)(base + (size_t)(r0 + m*16 + 8) * BB + col) = make_float2(acc[j][2], acc[j][3]);
                }
    } else {
        // ---------------- PRODUCER: LDG two stages ahead, store one ahead ----------------
        const int tp   = w * 32 + lane;         // 0..255
        const int prow = tp >> 4;               // rows prow + 16*i, i<8
        const int pf4  = tp & 15;

        float snx[8], sny[8];
        #pragma unroll
        for (int i = 0; i < 8; i++) { snx[i] = 0.f; sny[i] = 0.f; }

        float4 vx[2][4], vy[2][4];

        auto load_half = [&](int kt, int h) {
            const long long kb = (long long)kt * KT + pf4 * 4;
            #pragma unroll
            for (int i = 0; i < 4; i++) {
                const int row = prow + 16 * (4 * h + i);
                vx[h][i] = __ldg((const float4*)(X + (long long)row * DD + kb));
                vy[h][i] = __ldg((const float4*)(Y + (long long)row * DD + kb));
            }
        };
        auto store_half = [&](int p, int h) {
            char* xh = smem + TILE_OFF(p, 0);
            char* xl = smem + TILE_OFF(p, 1);
            char* yh = smem + TILE_OFF(p, 2);
            char* yl = smem + TILE_OFF(p, 3);
            #pragma unroll
            for (int i = 0; i < 4; i++) {
                const int ii = 4 * h + i;
                const int row = prow + 16 * ii;
                const uint32_t off = SW128(row * 128 + pf4 * 8);
                const float4 v = vx[h][i];
                snx[ii] += v.x*v.x + v.y*v.y + v.z*v.z + v.w*v.w;
                uint32_t h0, l0, h1, l1;
                cvt_hilo(v.x, v.y, h0, l0);
                cvt_hilo(v.z, v.w, h1, l1);
                *(uint2*)(xh + off) = make_uint2(h0, h1);
                *(uint2*)(xl + off) = make_uint2(l0, l1);
                const float4 u = vy[h][i];
                sny[ii] += u.x*u.x + u.y*u.y + u.z*u.z + u.w*u.w;
                cvt_hilo(u.x, u.y, h0, l0);
                cvt_hilo(u.z, u.w, h1, l1);
                *(uint2*)(yh + off) = make_uint2(h0, h1);
                *(uint2*)(yl + off) = make_uint2(l0, l1);
            }
        };

        load_half(t0, 0); load_half(t0, 1);
        store_half(0, 0); store_half(0, 1);
        if (NT > 1) { load_half(t0 + 1, 0); load_half(t0 + 1, 1); }
        __syncthreads();   // stage 0 ready

        for (int s = 0; s < NT; s++) {
            if (s + 1 < NT) {
                const int p = (s + 1) & 1;
                store_half(p, 0);
                if (s + 2 < NT) load_half(t0 + s + 2, 0);
                store_half(p, 1);
                if (s + 2 < NT) load_half(t0 + s + 2, 1);
            }
            __syncthreads();
        }

        // norm partials: 16 consecutive lanes share each row set
        #pragma unroll
        for (int i = 0; i < 8; i++) {
            float a = snx[i], b = sny[i];
            #pragma unroll
            for (int o = 8; o >= 1; o >>= 1) {
                a += __shfl_xor_sync(0xffffffffu, a, o);
                b += __shfl_xor_sync(0xffffffffu, b, o);
            }
            if (pf4 == 0) {
                const int row = prow + 16 * i;
                g_xn2p[c * BB + row] = a;
                g_yn2p[c * BB + row] = b;
            }
        }
    }
}

// Phase A: chunked reduction. 65536 threads: chunk ch sums CTAs [ch*37, ch*37+37).
__global__ void reduce_kernel() {
    const int gid = blockIdx.x * blockDim.x + threadIdx.x;   // 0..65535
    const int ch  = gid >> 14;
    const int idx = gid & 16383;
    if (gid == 0) { g_it1 = 0; g_it10 = 0; g_tick = 0; }
    const int c0 = ch * CPC;
    float s = 0.f;
    #pragma unroll
    for (int k = 0; k < CPC; k++) s += g_part[(size_t)(c0 + k) * (BB * BB) + idx];
    g_p2[idx * NCH + ch] = s;
    if (idx < BB) {
        float s2 = 0.f;
        #pragma unroll
        for (int k = 0; k < CPC; k++) s2 += g_xn2p[(c0 + k) * BB + idx];
        g_xc[idx * NCH + ch] = s2;
    } else if (idx < 2 * BB) {
        const int r = idx - BB;
        float s2 = 0.f;
        #pragma unroll
        for (int k = 0; k < CPC; k++) s2 += g_yn2p[(c0 + k) * BB + r];
        g_yc[r * NCH + ch] = s2;
    }
}

// parallel finalize: CTA j handles sim column j. JAX ties: lower index wins.
__global__ void finalize_kernel(float* __restrict__ out) {
    __shared__ float s_vd;
    __shared__ int s_gt, s_eqb;
    const int j = blockIdx.x;
    const int i = threadIdx.x;

    const float4 dv = *(const float4*)&g_p2[(i * BB + j) * NCH];
    const float dots = (dv.x + dv.y) + (dv.z + dv.w);
    const float4 xv = *(const float4*)&g_xc[i * NCH];
    const float xni = sqrtf((xv.x + xv.y) + (xv.z + xv.w));
    const float4 yv = *(const float4*)&g_yc[j * NCH];
    const float ynj = sqrtf((yv.x + yv.y) + (yv.z + yv.w));
    const float v = dots / fmaxf(xni * ynj, 1e-8f);

    if (i == 0) { s_gt = 0; s_eqb = 0; }
    if (i == j) s_vd = v;
    __syncthreads();
    const float vd = s_vd;

    const bool gt  = (i != j) && (v > vd);
    const bool eqb = (i != j) && (v == vd) && (i < j);
    const unsigned mgt  = __ballot_sync(0xffffffffu, gt);
    const unsigned meqb = __ballot_sync(0xffffffffu, eqb);
    if ((i & 31) == 0) {
        if (mgt)  atomicAdd(&s_gt,  __popc(mgt));
        if (meqb) atomicAdd(&s_eqb, __popc(meqb));
    }
    __syncthreads();

    if (i == 0) {
        const int rank = s_gt + s_eqb;
        atomicAdd(&g_it1,  (rank == 0) ? 1 : 0);
        atomicAdd(&g_it10, (rank < 10) ? 1 : 0);
        __threadfence();
        const int tick = atomicAdd(&g_tick, 1);
        if (tick == BB - 1) {
            __threadfence();
            out[0] = (float)g_it1  / (float)BB;
            out[1] = (float)g_it10 / (float)BB;
        }
    }
}

extern "C" void kernel_launch(void* const* d_in, const int* in_sizes, int n_in,
                              void* d_out, int out_size) {
    const float* Z = (const float*)d_in[0];
    const float* Y = (const float*)d_in[1];
    float* out = (float*)d_out;

    cudaFuncSetAttribute(gemm_tc_kernel, cudaFuncAttributeMaxDynamicSharedMemorySize, SMEM_TOTAL);
    gemm_tc_kernel<<<NCTA, THREADS, SMEM_TOTAL>>>(Z, Y);
    reduce_kernel<<<256, 256>>>();
    finalize_kernel<<<BB, BB>>>(out);
}